// round 6
// baseline (speedup 1.0000x reference)
#include <cuda_runtime.h>
#include <cuda_bf16.h>
#include <stdint.h>

// Problem constants
static constexpr int Bn = 4, Gn = 6, Hn = 8, Sn = 1024, DKn = 64, DMn = 512;
static constexpr int BG   = Bn * Gn;        // 24
static constexpr int BGH  = BG * Hn;        // 192
static constexpr int MROWS = BG * Sn;       // 24576
static constexpr int P_ELEMS = 201326592;   // 192*1024*1024
static constexpr int Y_ELEMS = BG * DMn;    // 12288

// Scratch (__device__ globals: allocation-free)
__device__ __align__(16) __nv_bfloat16 g_q[(size_t)MROWS * DMn];
__device__ __align__(16) __nv_bfloat16 g_k[(size_t)MROWS * DMn];
__device__ __align__(16) float g_wbar[BGH * Sn];
__device__ __align__(16) float g_t[BG * Hn * DMn];   // 24*8*512 partial t accum

__device__ __forceinline__ void mma16816(float c[4], const uint32_t a[4], const uint32_t b[2]) {
    asm volatile(
        "mma.sync.aligned.m16n8k16.row.col.f32.bf16.bf16.f32 "
        "{%0,%1,%2,%3},{%4,%5,%6,%7},{%8,%9},{%0,%1,%2,%3};\n"
        : "+f"(c[0]), "+f"(c[1]), "+f"(c[2]), "+f"(c[3])
        : "r"(a[0]), "r"(a[1]), "r"(a[2]), "r"(a[3]), "r"(b[0]), "r"(b[1]));
}

// ---------------------------------------------------------------------------
// Zero wbar (192*1024 floats) and g_t (24*4096 floats). grid 288 x 256thr x 4f
__global__ void zero_kernel() {
    int i = blockIdx.x * 1024 + threadIdx.x * 4;
    float4 z = make_float4(0.f, 0.f, 0.f, 0.f);
    if (i < BGH * Sn) *(float4*)&g_wbar[i] = z;
    else              *(float4*)&g_t[i - BGH * Sn] = z;
}

// ---------------------------------------------------------------------------
// Projection: y = x @ W^T + b, output bf16 in (bg, h, s, d) layout.
// Grid: (192 m-tiles, 4 n-tiles), 256 threads. Launched twice (which=0: Q, 1: K).
// NOTE: output symbol selected DEVICE-side (host code must not take the
// address of a __device__ variable — on GB300/ATS that silently writes the
// host shadow instead of device memory).
__global__ __launch_bounds__(256) void proj_kernel(
    const float* __restrict__ X, const float* __restrict__ W,
    const float* __restrict__ Bi, int which)
{
    __nv_bfloat16* __restrict__ O = which ? g_k : g_q;

    const int m0 = blockIdx.x * 128;
    const int n0 = blockIdx.y * 128;
    const int tid = threadIdx.x;
    const int w = tid >> 5, lane = tid & 31;
    const int gq = lane >> 2, tq = lane & 3;
    const int wm = w >> 1, wn = w & 1;   // 4x2 warp grid -> warp tile 32(m) x 64(n)

    __shared__ __nv_bfloat16 As[128 * 40];
    __shared__ __nv_bfloat16 Bs[128 * 40];

    float acc[2][8][4];
#pragma unroll
    for (int mi = 0; mi < 2; mi++)
#pragma unroll
        for (int ni = 0; ni < 8; ni++)
#pragma unroll
            for (int x = 0; x < 4; x++) acc[mi][ni][x] = 0.f;

    float4 ra[4], rb[4];
#pragma unroll
    for (int j = 0; j < 4; j++) {
        int i = tid + 256 * j;
        int r = i >> 3, c4 = (i & 7) * 4;
        ra[j] = *(const float4*)&X[(size_t)(m0 + r) * DMn + c4];
        rb[j] = *(const float4*)&W[(size_t)(n0 + r) * DMn + c4];
    }

    for (int kc = 0; kc < 16; kc++) {
        __syncthreads();
#pragma unroll
        for (int j = 0; j < 4; j++) {
            int i = tid + 256 * j;
            int r = i >> 3, c4 = (i & 7) * 4;
            __nv_bfloat162 lo = __floats2bfloat162_rn(ra[j].x, ra[j].y);
            __nv_bfloat162 hi = __floats2bfloat162_rn(ra[j].z, ra[j].w);
            *(__nv_bfloat162*)&As[r * 40 + c4]     = lo;
            *(__nv_bfloat162*)&As[r * 40 + c4 + 2] = hi;
            lo = __floats2bfloat162_rn(rb[j].x, rb[j].y);
            hi = __floats2bfloat162_rn(rb[j].z, rb[j].w);
            *(__nv_bfloat162*)&Bs[r * 40 + c4]     = lo;
            *(__nv_bfloat162*)&Bs[r * 40 + c4 + 2] = hi;
        }
        __syncthreads();
        if (kc < 15) {
            int kk = (kc + 1) * 32;
#pragma unroll
            for (int j = 0; j < 4; j++) {
                int i = tid + 256 * j;
                int r = i >> 3, c4 = (i & 7) * 4;
                ra[j] = *(const float4*)&X[(size_t)(m0 + r) * DMn + kk + c4];
                rb[j] = *(const float4*)&W[(size_t)(n0 + r) * DMn + kk + c4];
            }
        }
#pragma unroll
        for (int ks = 0; ks < 32; ks += 16) {
            uint32_t af[2][4];
#pragma unroll
            for (int mi = 0; mi < 2; mi++) {
                int ar = wm * 32 + mi * 16;
                af[mi][0] = *(const uint32_t*)&As[(ar + gq) * 40 + ks + 2 * tq];
                af[mi][1] = *(const uint32_t*)&As[(ar + gq + 8) * 40 + ks + 2 * tq];
                af[mi][2] = *(const uint32_t*)&As[(ar + gq) * 40 + ks + 2 * tq + 8];
                af[mi][3] = *(const uint32_t*)&As[(ar + gq + 8) * 40 + ks + 2 * tq + 8];
            }
#pragma unroll
            for (int ni = 0; ni < 8; ni++) {
                int br = wn * 64 + ni * 8 + gq;
                uint32_t bf[2];
                bf[0] = *(const uint32_t*)&Bs[br * 40 + ks + 2 * tq];
                bf[1] = *(const uint32_t*)&Bs[br * 40 + ks + 2 * tq + 8];
#pragma unroll
                for (int mi = 0; mi < 2; mi++) mma16816(acc[mi][ni], af[mi], bf);
            }
        }
    }

    // Epilogue: +bias, convert bf16, write to (bg,h,s,d) layout
#pragma unroll
    for (int ni = 0; ni < 8; ni++) {
        int cc = n0 + wn * 64 + ni * 8 + 2 * tq;
        float b0v = Bi[cc], b1v = Bi[cc + 1];
        int h = cc >> 6, d = cc & 63;
#pragma unroll
        for (int mi = 0; mi < 2; mi++) {
            int rbase = m0 + wm * 32 + mi * 16 + gq;
#pragma unroll
            for (int rr = 0; rr < 2; rr++) {
                int r = rbase + rr * 8;
                int bg = r >> 10, s = r & 1023;
                size_t off = ((size_t)(bg * Hn + h) * Sn + s) * DKn + d;
                float v0 = acc[mi][ni][rr * 2 + 0] + b0v;
                float v1 = acc[mi][ni][rr * 2 + 1] + b1v;
                *(__nv_bfloat162*)&O[off] = __floats2bfloat162_rn(v0, v1);
            }
        }
    }
}

// ---------------------------------------------------------------------------
// Attention v5b: fully register-resident. 16 q-rows x 1024 k per CTA; all 64
// exp values per thread live in registers (no e-tile). MMA -> exp in place ->
// rowsums -> invert -> normalize in regs -> direct gmem stores + shfl colsums.
static constexpr int QR   = 16;
static constexpr int KSTR = 72;

__global__ __launch_bounds__(256, 2) void attn_kernel(float* __restrict__ out, int p_base, int write_p)
{
    __shared__ __nv_bfloat16 qs[QR * KSTR];
    __shared__ __nv_bfloat16 ksm[2 * 128 * KSTR];
    __shared__ float rsum[QR];

    const int qt = blockIdx.x, bgh = blockIdx.y;
    const int tid = threadIdx.x;
    const int w = tid >> 5, lane = tid & 31;
    const int gq = lane >> 2, tq = lane & 3;

    const __nv_bfloat16* qbase = g_q + (size_t)bgh * (Sn * DKn) + (size_t)qt * QR * DKn;
    const __nv_bfloat16* kbase = g_k + (size_t)bgh * (Sn * DKn);

    if (tid < 128) {
        int r = tid >> 3, part = tid & 7;
        *(uint4*)&qs[r * KSTR + part * 8] = *(const uint4*)&qbase[r * DKn + part * 8];
    }
    if (tid < QR) rsum[tid] = 0.f;

    const float SCL = 1.0f / 1200.0f;  // 1/(sqrt(64)*150)
    const int ldr = tid >> 3, ldp = (tid & 7) * 8;

    uint4 pre[4];
#pragma unroll
    for (int j = 0; j < 4; j++)
        pre[j] = *(const uint4*)&kbase[(size_t)(ldr + 32 * j) * DKn + ldp];

    float acc[8][2][4];
#pragma unroll
    for (int c = 0; c < 8; c++)
#pragma unroll
        for (int ni = 0; ni < 2; ni++)
#pragma unroll
            for (int x = 0; x < 4; x++) acc[c][ni][x] = 0.f;

    uint32_t aq[4][4];    // q fragments, loaded once
    float rs0 = 0.f, rs1 = 0.f;

#pragma unroll
    for (int c = 0; c < 8; c++) {
        __nv_bfloat16* kbuf = ksm + (c & 1) * 128 * KSTR;
#pragma unroll
        for (int j = 0; j < 4; j++)
            *(uint4*)&kbuf[(ldr + 32 * j) * KSTR + ldp] = pre[j];
        __syncthreads();
        if (c == 0) {
#pragma unroll
            for (int k4 = 0; k4 < 4; k4++) {
                int ks = k4 * 16;
                aq[k4][0] = *(const uint32_t*)&qs[gq * KSTR + ks + 2 * tq];
                aq[k4][1] = *(const uint32_t*)&qs[(gq + 8) * KSTR + ks + 2 * tq];
                aq[k4][2] = *(const uint32_t*)&qs[gq * KSTR + ks + 2 * tq + 8];
                aq[k4][3] = *(const uint32_t*)&qs[(gq + 8) * KSTR + ks + 2 * tq + 8];
            }
        }
        if (c < 7) {
#pragma unroll
            for (int j = 0; j < 4; j++)
                pre[j] = *(const uint4*)&kbase[(size_t)((c + 1) * 128 + ldr + 32 * j) * DKn + ldp];
        }

#pragma unroll
        for (int k4 = 0; k4 < 4; k4++) {
            int ks = k4 * 16;
#pragma unroll
            for (int ni = 0; ni < 2; ni++) {
                int br = w * 16 + ni * 8 + gq;
                uint32_t bf[2];
                bf[0] = *(const uint32_t*)&kbuf[br * KSTR + ks + 2 * tq];
                bf[1] = *(const uint32_t*)&kbuf[br * KSTR + ks + 2 * tq + 8];
                mma16816(acc[c][ni], aq[k4], bf);
            }
        }

        // exp in place + rowsum partials
#pragma unroll
        for (int ni = 0; ni < 2; ni++) {
            float e0 = __expf(acc[c][ni][0] * SCL);
            float e1 = __expf(acc[c][ni][1] * SCL);
            float e2 = __expf(acc[c][ni][2] * SCL);
            float e3 = __expf(acc[c][ni][3] * SCL);
            acc[c][ni][0] = e0; acc[c][ni][1] = e1;
            acc[c][ni][2] = e2; acc[c][ni][3] = e3;
            rs0 += e0 + e1;
            rs1 += e2 + e3;
        }
    }

    // rowsum reduce: over tq quad, then across warps via smem
    rs0 += __shfl_xor_sync(0xffffffffu, rs0, 1);
    rs0 += __shfl_xor_sync(0xffffffffu, rs0, 2);
    rs1 += __shfl_xor_sync(0xffffffffu, rs1, 1);
    rs1 += __shfl_xor_sync(0xffffffffu, rs1, 2);
    if (tq == 0) {
        atomicAdd(&rsum[gq], rs0);
        atomicAdd(&rsum[gq + 8], rs1);
    }
    __syncthreads();
    if (tid < QR) rsum[tid] = 1.0f / rsum[tid];
    __syncthreads();

    const float inv0 = rsum[gq], inv1 = rsum[gq + 8];
    float* pout = out + p_base + (size_t)bgh * ((size_t)Sn * Sn) + (size_t)(qt * QR) * Sn;
    float* wbar = g_wbar + bgh * Sn;

#pragma unroll
    for (int c = 0; c < 8; c++) {
#pragma unroll
        for (int ni = 0; ni < 2; ni++) {
            int col = c * 128 + w * 16 + ni * 8 + 2 * tq;
            float v00 = acc[c][ni][0] * inv0, v01 = acc[c][ni][1] * inv0;
            float v10 = acc[c][ni][2] * inv1, v11 = acc[c][ni][3] * inv1;
            if (write_p) {
                *(float2*)&pout[(size_t)gq * Sn + col]       = make_float2(v00, v01);
                *(float2*)&pout[(size_t)(gq + 8) * Sn + col] = make_float2(v10, v11);
            }
            // column sums: reduce over gq (lane bits 2..4)
            float csx = v00 + v10, csy = v01 + v11;
            csx += __shfl_xor_sync(0xffffffffu, csx, 4);
            csx += __shfl_xor_sync(0xffffffffu, csx, 8);
            csx += __shfl_xor_sync(0xffffffffu, csx, 16);
            csy += __shfl_xor_sync(0xffffffffu, csy, 4);
            csy += __shfl_xor_sync(0xffffffffu, csy, 8);
            csy += __shfl_xor_sync(0xffffffffu, csy, 16);
            if (lane < 4) {
                atomicAdd(&wbar[col], csx);
                atomicAdd(&wbar[col + 1], csy);
            }
        }
    }
}

// ---------------------------------------------------------------------------
// t = (wbar/1024) @ Xv, parallelized over (bg, 16 S-chunks of 64).
__global__ __launch_bounds__(256) void t_kernel(const float* __restrict__ value)
{
    __shared__ float wb[8][64];
    const int bg = blockIdx.x, kc = blockIdx.y;
    const int tid = threadIdx.x;

    for (int j = tid; j < 512; j += 256) {
        int h = j >> 6, k = j & 63;
        wb[h][k] = g_wbar[(bg * 8 + h) * Sn + kc * 64 + k] * (1.0f / 1024.0f);
    }
    __syncthreads();

    float a[8][2];
#pragma unroll
    for (int h = 0; h < 8; h++) { a[h][0] = 0.f; a[h][1] = 0.f; }

    const float* __restrict__ xv = value + (size_t)bg * (Sn * DMn) + (size_t)(kc * 64) * DMn;
#pragma unroll 4
    for (int k = 0; k < 64; k++) {
        float x0 = xv[k * DMn + tid];
        float x1 = xv[k * DMn + tid + 256];
#pragma unroll
        for (int h = 0; h < 8; h++) {
            a[h][0] += wb[h][k] * x0;
            a[h][1] += wb[h][k] * x1;
        }
    }
#pragma unroll
    for (int h = 0; h < 8; h++) {
        atomicAdd(&g_t[(bg * 8 + h) * DMn + tid],       a[h][0]);
        atomicAdd(&g_t[(bg * 8 + h) * DMn + tid + 256], a[h][1]);
    }
}

// ---------------------------------------------------------------------------
// finalize2: out_hd = t_h . Wv[h*64+d] + bv ; f[d*8+h] = out_hd ;
// y = f @ Wo^T + bo.  One CTA per (b,g), 512 threads, row-contiguous W loads.
__global__ __launch_bounds__(512) void finalize2_kernel(
    const float* __restrict__ Wv, const float* __restrict__ bv,
    const float* __restrict__ Wo, const float* __restrict__ bo,
    float* __restrict__ out, int write_y)
{
    __shared__ float ts[8 * 512];
    __shared__ float fs[512];
    const int bg = blockIdx.x, tid = threadIdx.x;

#pragma unroll
    for (int j = 0; j < 8; j++) ts[j * 512 + tid] = g_t[bg * 4096 + j * 512 + tid];
    __syncthreads();

    {
        int h = tid >> 6, d = tid & 63;
        const float4* __restrict__ wr = (const float4*)(Wv + (size_t)tid * DMn);
        const float* th = ts + h * 512;
        float o0 = 0, o1 = 0, o2 = 0, o3 = 0;
#pragma unroll 8
        for (int c = 0; c < 128; c++) {
            float4 w4 = wr[c];
            o0 += th[4 * c + 0] * w4.x;
            o1 += th[4 * c + 1] * w4.y;
            o2 += th[4 * c + 2] * w4.z;
            o3 += th[4 * c + 3] * w4.w;
        }
        fs[d * 8 + h] = bv[tid] + ((o0 + o1) + (o2 + o3));
    }
    __syncthreads();

    if (write_y) {
        const float4* __restrict__ wr = (const float4*)(Wo + (size_t)tid * DMn);
        float o0 = 0, o1 = 0, o2 = 0, o3 = 0;
#pragma unroll 8
        for (int c = 0; c < 128; c++) {
            float4 w4 = wr[c];
            o0 += fs[4 * c + 0] * w4.x;
            o1 += fs[4 * c + 1] * w4.y;
            o2 += fs[4 * c + 2] * w4.z;
            o3 += fs[4 * c + 3] * w4.w;
        }
        out[bg * DMn + tid] = bo[tid] + ((o0 + o1) + (o2 + o3));
    }
}

// ---------------------------------------------------------------------------
extern "C" void kernel_launch(void* const* d_in, const int* in_sizes, int n_in,
                              void* d_out, int out_size)
{
    if (n_in < 11) return;
    const float* query = (const float*)d_in[0];
    const float* key   = (const float*)d_in[1];
    const float* value = (const float*)d_in[2];
    const float* Wq = (const float*)d_in[3];
    const float* bq = (const float*)d_in[4];
    const float* Wk = (const float*)d_in[5];
    const float* bk = (const float*)d_in[6];
    const float* Wv = (const float*)d_in[7];
    const float* bv = (const float*)d_in[8];
    const float* Wo = (const float*)d_in[9];
    const float* bo = (const float*)d_in[10];
    float* out = (float*)d_out;

    const int write_p = (out_size >= P_ELEMS) ? 1 : 0;
    const int p_base  = (out_size > P_ELEMS) ? Y_ELEMS : 0;
    const int write_y = (out_size == Y_ELEMS || out_size == Y_ELEMS + P_ELEMS) ? 1 : 0;

    zero_kernel<<<288, 256>>>();
    proj_kernel<<<dim3(192, 4), 256>>>(query, Wq, bq, 0);      // -> g_q
    proj_kernel<<<dim3(192, 4), 256>>>(key,   Wk, bk, 1);      // -> g_k
    attn_kernel<<<dim3(64, 192), 256>>>(out, p_base, write_p);
    t_kernel<<<dim3(BG, 16), 256>>>(value);
    finalize2_kernel<<<BG, 512>>>(Wv, bv, Wo, bo, out, write_y);
}

// round 8
// speedup vs baseline: 1.0520x; 1.0520x over previous
#include <cuda_runtime.h>
#include <cuda_bf16.h>
#include <stdint.h>

// Problem constants
static constexpr int Bn = 4, Gn = 6, Hn = 8, Sn = 1024, DKn = 64, DMn = 512;
static constexpr int BG   = Bn * Gn;        // 24
static constexpr int BGH  = BG * Hn;        // 192
static constexpr int MROWS = BG * Sn;       // 24576
static constexpr int P_ELEMS = 201326592;   // 192*1024*1024
static constexpr int Y_ELEMS = BG * DMn;    // 12288

// Scratch (__device__ globals: allocation-free)
__device__ __align__(16) __nv_bfloat16 g_xq[(size_t)MROWS * DMn];  // bf16 inputs
__device__ __align__(16) __nv_bfloat16 g_xk[(size_t)MROWS * DMn];
__device__ __align__(16) __nv_bfloat16 g_wq[DMn * DMn];
__device__ __align__(16) __nv_bfloat16 g_wk[DMn * DMn];
__device__ __align__(16) __nv_bfloat16 g_q[(size_t)MROWS * DMn];   // (bg,h,s,d)
__device__ __align__(16) __nv_bfloat16 g_k[(size_t)MROWS * DMn];
__device__ __align__(16) float g_wbar[BGH * Sn];
__device__ __align__(16) float g_t[BG * Hn * DMn];

__device__ __forceinline__ void mma16816(float c[4], const uint32_t a[4], const uint32_t b[2]) {
    asm volatile(
        "mma.sync.aligned.m16n8k16.row.col.f32.bf16.bf16.f32 "
        "{%0,%1,%2,%3},{%4,%5,%6,%7},{%8,%9},{%0,%1,%2,%3};\n"
        : "+f"(c[0]), "+f"(c[1]), "+f"(c[2]), "+f"(c[3])
        : "r"(a[0]), "r"(a[1]), "r"(a[2]), "r"(a[3]), "r"(b[0]), "r"(b[1]));
}

// ---------------------------------------------------------------------------
__global__ void zero_kernel() {
    int i = blockIdx.x * 1024 + threadIdx.x * 4;
    float4 z = make_float4(0.f, 0.f, 0.f, 0.f);
    if (i < BGH * Sn) *(float4*)&g_wbar[i] = z;
    else              *(float4*)&g_t[i - BGH * Sn] = z;
}

// ---------------------------------------------------------------------------
// fp32 -> bf16 conversion, 8 elements/thread. which: 0=xq 1=xk 2=wq 3=wk.
__global__ __launch_bounds__(256) void conv_kernel(const float* __restrict__ src, int which, int n8)
{
    int i = blockIdx.x * 256 + threadIdx.x;
    if (i >= n8) return;
    __nv_bfloat16* dst = (which == 0) ? g_xq : (which == 1) ? g_xk
                       : (which == 2) ? g_wq : g_wk;
    float4 a = ((const float4*)src)[i * 2];
    float4 b = ((const float4*)src)[i * 2 + 1];
    uint4 o;
    __nv_bfloat162 t0 = __floats2bfloat162_rn(a.x, a.y);
    __nv_bfloat162 t1 = __floats2bfloat162_rn(a.z, a.w);
    __nv_bfloat162 t2 = __floats2bfloat162_rn(b.x, b.y);
    __nv_bfloat162 t3 = __floats2bfloat162_rn(b.z, b.w);
    o.x = *(uint32_t*)&t0; o.y = *(uint32_t*)&t1;
    o.z = *(uint32_t*)&t2; o.w = *(uint32_t*)&t3;
    ((uint4*)dst)[i] = o;
}

// ---------------------------------------------------------------------------
// Projection v2: all-bf16. y = x @ W^T + b -> (bg,h,s,d) bf16.
// 64-wide k-chunks (8 iters), stride-72 smem, reg-prefetch. Grid (192,4).
__global__ __launch_bounds__(256) void proj_kernel(const float* __restrict__ Bi, int which)
{
    const __nv_bfloat16* __restrict__ X = which ? g_xk : g_xq;
    const __nv_bfloat16* __restrict__ W = which ? g_wk : g_wq;
    __nv_bfloat16* __restrict__ O = which ? g_k : g_q;

    const int m0 = blockIdx.x * 128;
    const int n0 = blockIdx.y * 128;
    const int tid = threadIdx.x;
    const int w = tid >> 5, lane = tid & 31;
    const int gq = lane >> 2, tq = lane & 3;
    const int wm = w >> 1, wn = w & 1;   // 4x2 warps -> warp tile 32(m) x 64(n)

    __shared__ __nv_bfloat16 As[128 * 72];
    __shared__ __nv_bfloat16 Bs[128 * 72];

    float acc[2][8][4];
#pragma unroll
    for (int mi = 0; mi < 2; mi++)
#pragma unroll
        for (int ni = 0; ni < 8; ni++)
#pragma unroll
            for (int x = 0; x < 4; x++) acc[mi][ni][x] = 0.f;

    const int ldr = tid >> 3, ldc = (tid & 7) * 8;   // loader: row, col8
    uint4 ra[4], rb[4];
#pragma unroll
    for (int j = 0; j < 4; j++) {
        int r = ldr + 32 * j;
        ra[j] = *(const uint4*)&X[(size_t)(m0 + r) * DMn + ldc];
        rb[j] = *(const uint4*)&W[(size_t)(n0 + r) * DMn + ldc];
    }

    for (int kc = 0; kc < 8; kc++) {
        __syncthreads();
#pragma unroll
        for (int j = 0; j < 4; j++) {
            int r = ldr + 32 * j;
            *(uint4*)&As[r * 72 + ldc] = ra[j];
            *(uint4*)&Bs[r * 72 + ldc] = rb[j];
        }
        __syncthreads();
        if (kc < 7) {
            int kk = (kc + 1) * 64;
#pragma unroll
            for (int j = 0; j < 4; j++) {
                int r = ldr + 32 * j;
                ra[j] = *(const uint4*)&X[(size_t)(m0 + r) * DMn + kk + ldc];
                rb[j] = *(const uint4*)&W[(size_t)(n0 + r) * DMn + kk + ldc];
            }
        }
#pragma unroll
        for (int ks = 0; ks < 64; ks += 16) {
            uint32_t af[2][4];
#pragma unroll
            for (int mi = 0; mi < 2; mi++) {
                int ar = wm * 32 + mi * 16;
                af[mi][0] = *(const uint32_t*)&As[(ar + gq) * 72 + ks + 2 * tq];
                af[mi][1] = *(const uint32_t*)&As[(ar + gq + 8) * 72 + ks + 2 * tq];
                af[mi][2] = *(const uint32_t*)&As[(ar + gq) * 72 + ks + 2 * tq + 8];
                af[mi][3] = *(const uint32_t*)&As[(ar + gq + 8) * 72 + ks + 2 * tq + 8];
            }
#pragma unroll
            for (int ni = 0; ni < 8; ni++) {
                int br = wn * 64 + ni * 8 + gq;
                uint32_t bf[2];
                bf[0] = *(const uint32_t*)&Bs[br * 72 + ks + 2 * tq];
                bf[1] = *(const uint32_t*)&Bs[br * 72 + ks + 2 * tq + 8];
#pragma unroll
                for (int mi = 0; mi < 2; mi++) mma16816(acc[mi][ni], af[mi], bf);
            }
        }
    }

    // Epilogue: +bias, convert bf16, write to (bg,h,s,d) layout
#pragma unroll
    for (int ni = 0; ni < 8; ni++) {
        int cc = n0 + wn * 64 + ni * 8 + 2 * tq;
        float b0v = Bi[cc], b1v = Bi[cc + 1];
        int h = cc >> 6, d = cc & 63;
#pragma unroll
        for (int mi = 0; mi < 2; mi++) {
            int rbase = m0 + wm * 32 + mi * 16 + gq;
#pragma unroll
            for (int rr = 0; rr < 2; rr++) {
                int r = rbase + rr * 8;
                int bg = r >> 10, s = r & 1023;
                size_t off = ((size_t)(bg * Hn + h) * Sn + s) * DKn + d;
                float v0 = acc[mi][ni][rr * 2 + 0] + b0v;
                float v1 = acc[mi][ni][rr * 2 + 1] + b1v;
                *(__nv_bfloat162*)&O[off] = __floats2bfloat162_rn(v0, v1);
            }
        }
    }
}

// ---------------------------------------------------------------------------
// Attention (round-6, validated): register-resident exp, smem K staging.
static constexpr int QR   = 16;
static constexpr int KSTR = 72;

__global__ __launch_bounds__(256, 2) void attn_kernel(float* __restrict__ out, int p_base, int write_p)
{
    __shared__ __nv_bfloat16 qs[QR * KSTR];
    __shared__ __nv_bfloat16 ksm[2 * 128 * KSTR];
    __shared__ float rsum[QR];

    const int qt = blockIdx.x, bgh = blockIdx.y;
    const int tid = threadIdx.x;
    const int w = tid >> 5, lane = tid & 31;
    const int gq = lane >> 2, tq = lane & 3;

    const __nv_bfloat16* qbase = g_q + (size_t)bgh * (Sn * DKn) + (size_t)qt * QR * DKn;
    const __nv_bfloat16* kbase = g_k + (size_t)bgh * (Sn * DKn);

    if (tid < 128) {
        int r = tid >> 3, part = tid & 7;
        *(uint4*)&qs[r * KSTR + part * 8] = *(const uint4*)&qbase[r * DKn + part * 8];
    }
    if (tid < QR) rsum[tid] = 0.f;

    const float SCL = 1.0f / 1200.0f;  // 1/(sqrt(64)*150)
    const int ldr = tid >> 3, ldp = (tid & 7) * 8;

    uint4 pre[4];
#pragma unroll
    for (int j = 0; j < 4; j++)
        pre[j] = *(const uint4*)&kbase[(size_t)(ldr + 32 * j) * DKn + ldp];

    float acc[8][2][4];
#pragma unroll
    for (int c = 0; c < 8; c++)
#pragma unroll
        for (int ni = 0; ni < 2; ni++)
#pragma unroll
            for (int x = 0; x < 4; x++) acc[c][ni][x] = 0.f;

    uint32_t aq[4][4];
    float rs0 = 0.f, rs1 = 0.f;

#pragma unroll
    for (int c = 0; c < 8; c++) {
        __nv_bfloat16* kbuf = ksm + (c & 1) * 128 * KSTR;
#pragma unroll
        for (int j = 0; j < 4; j++)
            *(uint4*)&kbuf[(ldr + 32 * j) * KSTR + ldp] = pre[j];
        __syncthreads();
        if (c == 0) {
#pragma unroll
            for (int k4 = 0; k4 < 4; k4++) {
                int ks = k4 * 16;
                aq[k4][0] = *(const uint32_t*)&qs[gq * KSTR + ks + 2 * tq];
                aq[k4][1] = *(const uint32_t*)&qs[(gq + 8) * KSTR + ks + 2 * tq];
                aq[k4][2] = *(const uint32_t*)&qs[gq * KSTR + ks + 2 * tq + 8];
                aq[k4][3] = *(const uint32_t*)&qs[(gq + 8) * KSTR + ks + 2 * tq + 8];
            }
        }
        if (c < 7) {
#pragma unroll
            for (int j = 0; j < 4; j++)
                pre[j] = *(const uint4*)&kbase[(size_t)((c + 1) * 128 + ldr + 32 * j) * DKn + ldp];
        }

#pragma unroll
        for (int k4 = 0; k4 < 4; k4++) {
            int ks = k4 * 16;
#pragma unroll
            for (int ni = 0; ni < 2; ni++) {
                int br = w * 16 + ni * 8 + gq;
                uint32_t bf[2];
                bf[0] = *(const uint32_t*)&kbuf[br * KSTR + ks + 2 * tq];
                bf[1] = *(const uint32_t*)&kbuf[br * KSTR + ks + 2 * tq + 8];
                mma16816(acc[c][ni], aq[k4], bf);
            }
        }

#pragma unroll
        for (int ni = 0; ni < 2; ni++) {
            float e0 = __expf(acc[c][ni][0] * SCL);
            float e1 = __expf(acc[c][ni][1] * SCL);
            float e2 = __expf(acc[c][ni][2] * SCL);
            float e3 = __expf(acc[c][ni][3] * SCL);
            acc[c][ni][0] = e0; acc[c][ni][1] = e1;
            acc[c][ni][2] = e2; acc[c][ni][3] = e3;
            rs0 += e0 + e1;
            rs1 += e2 + e3;
        }
    }

    rs0 += __shfl_xor_sync(0xffffffffu, rs0, 1);
    rs0 += __shfl_xor_sync(0xffffffffu, rs0, 2);
    rs1 += __shfl_xor_sync(0xffffffffu, rs1, 1);
    rs1 += __shfl_xor_sync(0xffffffffu, rs1, 2);
    if (tq == 0) {
        atomicAdd(&rsum[gq], rs0);
        atomicAdd(&rsum[gq + 8], rs1);
    }
    __syncthreads();
    if (tid < QR) rsum[tid] = 1.0f / rsum[tid];
    __syncthreads();

    const float inv0 = rsum[gq], inv1 = rsum[gq + 8];
    float* pout = out + p_base + (size_t)bgh * ((size_t)Sn * Sn) + (size_t)(qt * QR) * Sn;
    float* wbar = g_wbar + bgh * Sn;

#pragma unroll
    for (int c = 0; c < 8; c++) {
#pragma unroll
        for (int ni = 0; ni < 2; ni++) {
            int col = c * 128 + w * 16 + ni * 8 + 2 * tq;
            float v00 = acc[c][ni][0] * inv0, v01 = acc[c][ni][1] * inv0;
            float v10 = acc[c][ni][2] * inv1, v11 = acc[c][ni][3] * inv1;
            if (write_p) {
                *(float2*)&pout[(size_t)gq * Sn + col]       = make_float2(v00, v01);
                *(float2*)&pout[(size_t)(gq + 8) * Sn + col] = make_float2(v10, v11);
            }
            float csx = v00 + v10, csy = v01 + v11;
            csx += __shfl_xor_sync(0xffffffffu, csx, 4);
            csx += __shfl_xor_sync(0xffffffffu, csx, 8);
            csx += __shfl_xor_sync(0xffffffffu, csx, 16);
            csy += __shfl_xor_sync(0xffffffffu, csy, 4);
            csy += __shfl_xor_sync(0xffffffffu, csy, 8);
            csy += __shfl_xor_sync(0xffffffffu, csy, 16);
            if (lane < 4) {
                atomicAdd(&wbar[col], csx);
                atomicAdd(&wbar[col + 1], csy);
            }
        }
    }
}

// ---------------------------------------------------------------------------
__global__ __launch_bounds__(256) void t_kernel(const float* __restrict__ value)
{
    __shared__ float wb[8][64];
    const int bg = blockIdx.x, kc = blockIdx.y;
    const int tid = threadIdx.x;

    for (int j = tid; j < 512; j += 256) {
        int h = j >> 6, k = j & 63;
        wb[h][k] = g_wbar[(bg * 8 + h) * Sn + kc * 64 + k] * (1.0f / 1024.0f);
    }
    __syncthreads();

    float a[8][2];
#pragma unroll
    for (int h = 0; h < 8; h++) { a[h][0] = 0.f; a[h][1] = 0.f; }

    const float* __restrict__ xv = value + (size_t)bg * (Sn * DMn) + (size_t)(kc * 64) * DMn;
#pragma unroll 4
    for (int k = 0; k < 64; k++) {
        float x0 = xv[k * DMn + tid];
        float x1 = xv[k * DMn + tid + 256];
#pragma unroll
        for (int h = 0; h < 8; h++) {
            a[h][0] += wb[h][k] * x0;
            a[h][1] += wb[h][k] * x1;
        }
    }
#pragma unroll
    for (int h = 0; h < 8; h++) {
        atomicAdd(&g_t[(bg * 8 + h) * DMn + tid],       a[h][0]);
        atomicAdd(&g_t[(bg * 8 + h) * DMn + tid + 256], a[h][1]);
    }
}

// ---------------------------------------------------------------------------
__global__ __launch_bounds__(512) void finalize2_kernel(
    const float* __restrict__ Wv, const float* __restrict__ bv,
    const float* __restrict__ Wo, const float* __restrict__ bo,
    float* __restrict__ out, int write_y)
{
    __shared__ float ts[8 * 512];
    __shared__ float fs[512];
    const int bg = blockIdx.x, tid = threadIdx.x;

#pragma unroll
    for (int j = 0; j < 8; j++) ts[j * 512 + tid] = g_t[bg * 4096 + j * 512 + tid];
    __syncthreads();

    {
        int h = tid >> 6, d = tid & 63;
        const float4* __restrict__ wr = (const float4*)(Wv + (size_t)tid * DMn);
        const float* th = ts + h * 512;
        float o0 = 0, o1 = 0, o2 = 0, o3 = 0;
#pragma unroll 8
        for (int c = 0; c < 128; c++) {
            float4 w4 = wr[c];
            o0 += th[4 * c + 0] * w4.x;
            o1 += th[4 * c + 1] * w4.y;
            o2 += th[4 * c + 2] * w4.z;
            o3 += th[4 * c + 3] * w4.w;
        }
        fs[d * 8 + h] = bv[tid] + ((o0 + o1) + (o2 + o3));
    }
    __syncthreads();

    if (write_y) {
        const float4* __restrict__ wr = (const float4*)(Wo + (size_t)tid * DMn);
        float o0 = 0, o1 = 0, o2 = 0, o3 = 0;
#pragma unroll 8
        for (int c = 0; c < 128; c++) {
            float4 w4 = wr[c];
            o0 += fs[4 * c + 0] * w4.x;
            o1 += fs[4 * c + 1] * w4.y;
            o2 += fs[4 * c + 2] * w4.z;
            o3 += fs[4 * c + 3] * w4.w;
        }
        out[bg * DMn + tid] = bo[tid] + ((o0 + o1) + (o2 + o3));
    }
}

// ---------------------------------------------------------------------------
extern "C" void kernel_launch(void* const* d_in, const int* in_sizes, int n_in,
                              void* d_out, int out_size)
{
    if (n_in < 11) return;
    const float* query = (const float*)d_in[0];
    const float* key   = (const float*)d_in[1];
    const float* value = (const float*)d_in[2];
    const float* Wq = (const float*)d_in[3];
    const float* bq = (const float*)d_in[4];
    const float* Wk = (const float*)d_in[5];
    const float* bk = (const float*)d_in[6];
    const float* Wv = (const float*)d_in[7];
    const float* bv = (const float*)d_in[8];
    const float* Wo = (const float*)d_in[9];
    const float* bo = (const float*)d_in[10];
    float* out = (float*)d_out;

    const int write_p = (out_size >= P_ELEMS) ? 1 : 0;
    const int p_base  = (out_size > P_ELEMS) ? Y_ELEMS : 0;
    const int write_y = (out_size == Y_ELEMS || out_size == Y_ELEMS + P_ELEMS) ? 1 : 0;

    const int X8 = (MROWS * DMn) / 8;      // 1572864
    const int W8 = (DMn * DMn) / 8;        // 32768

    zero_kernel<<<288, 256>>>();
    conv_kernel<<<X8 / 256, 256>>>(query, 0, X8);
    conv_kernel<<<X8 / 256, 256>>>(key,   1, X8);
    conv_kernel<<<W8 / 256, 256>>>(Wq,    2, W8);
    conv_kernel<<<W8 / 256, 256>>>(Wk,    3, W8);
    proj_kernel<<<dim3(192, 4), 256>>>(bq, 0);   // -> g_q
    proj_kernel<<<dim3(192, 4), 256>>>(bk, 1);   // -> g_k
    attn_kernel<<<dim3(64, 192), 256>>>(out, p_base, write_p);
    t_kernel<<<dim3(BG, 16), 256>>>(value);
    finalize2_kernel<<<BG, 512>>>(Wv, bv, Wo, bo, out, write_y);
}

// round 9
// speedup vs baseline: 1.0601x; 1.0077x over previous
#include <cuda_runtime.h>
#include <cuda_bf16.h>
#include <stdint.h>

// Problem constants
static constexpr int Bn = 4, Gn = 6, Hn = 8, Sn = 1024, DKn = 64, DMn = 512;
static constexpr int BG   = Bn * Gn;        // 24
static constexpr int BGH  = BG * Hn;        // 192
static constexpr int MROWS = BG * Sn;       // 24576
static constexpr int P_ELEMS = 201326592;   // 192*1024*1024
static constexpr int Y_ELEMS = BG * DMn;    // 12288

// Scratch (__device__ globals: allocation-free)
__device__ __align__(16) __nv_bfloat16 g_xq[(size_t)MROWS * DMn];  // bf16 inputs
__device__ __align__(16) __nv_bfloat16 g_xk[(size_t)MROWS * DMn];
__device__ __align__(16) __nv_bfloat16 g_wq[DMn * DMn];
__device__ __align__(16) __nv_bfloat16 g_wk[DMn * DMn];
__device__ __align__(16) __nv_bfloat16 g_q[(size_t)MROWS * DMn];   // (bg,h,s,d)
__device__ __align__(16) __nv_bfloat16 g_k[(size_t)MROWS * DMn];
__device__ __align__(16) float g_wbar[BGH * Sn];
__device__ __align__(16) float g_t[BG * Hn * DMn];

__device__ __forceinline__ void mma16816(float c[4], const uint32_t a[4], const uint32_t b[2]) {
    asm volatile(
        "mma.sync.aligned.m16n8k16.row.col.f32.bf16.bf16.f32 "
        "{%0,%1,%2,%3},{%4,%5,%6,%7},{%8,%9},{%0,%1,%2,%3};\n"
        : "+f"(c[0]), "+f"(c[1]), "+f"(c[2]), "+f"(c[3])
        : "r"(a[0]), "r"(a[1]), "r"(a[2]), "r"(a[3]), "r"(b[0]), "r"(b[1]));
}

// ---------------------------------------------------------------------------
__global__ void zero_kernel() {
    int i = blockIdx.x * 1024 + threadIdx.x * 4;
    float4 z = make_float4(0.f, 0.f, 0.f, 0.f);
    if (i < BGH * Sn) *(float4*)&g_wbar[i] = z;
    else              *(float4*)&g_t[i - BGH * Sn] = z;
}

// ---------------------------------------------------------------------------
// fp32 -> bf16 conversion, 8 elements/thread. which: 0=xq 1=xk 2=wq 3=wk.
__global__ __launch_bounds__(256) void conv_kernel(const float* __restrict__ src, int which, int n8)
{
    int i = blockIdx.x * 256 + threadIdx.x;
    if (i >= n8) return;
    __nv_bfloat16* dst = (which == 0) ? g_xq : (which == 1) ? g_xk
                       : (which == 2) ? g_wq : g_wk;
    float4 a = ((const float4*)src)[i * 2];
    float4 b = ((const float4*)src)[i * 2 + 1];
    uint4 o;
    __nv_bfloat162 t0 = __floats2bfloat162_rn(a.x, a.y);
    __nv_bfloat162 t1 = __floats2bfloat162_rn(a.z, a.w);
    __nv_bfloat162 t2 = __floats2bfloat162_rn(b.x, b.y);
    __nv_bfloat162 t3 = __floats2bfloat162_rn(b.z, b.w);
    o.x = *(uint32_t*)&t0; o.y = *(uint32_t*)&t1;
    o.z = *(uint32_t*)&t2; o.w = *(uint32_t*)&t3;
    ((uint4*)dst)[i] = o;
}

// ---------------------------------------------------------------------------
// Projection: all-bf16. y = x @ W^T + b -> (bg,h,s,d) bf16.
// 64-wide k-chunks (8 iters), stride-72 smem, reg-prefetch. Grid (192,4).
__global__ __launch_bounds__(256) void proj_kernel(const float* __restrict__ Bi, int which)
{
    const __nv_bfloat16* __restrict__ X = which ? g_xk : g_xq;
    const __nv_bfloat16* __restrict__ W = which ? g_wk : g_wq;
    __nv_bfloat16* __restrict__ O = which ? g_k : g_q;

    const int m0 = blockIdx.x * 128;
    const int n0 = blockIdx.y * 128;
    const int tid = threadIdx.x;
    const int w = tid >> 5, lane = tid & 31;
    const int gq = lane >> 2, tq = lane & 3;
    const int wm = w >> 1, wn = w & 1;   // 4x2 warps -> warp tile 32(m) x 64(n)

    __shared__ __nv_bfloat16 As[128 * 72];
    __shared__ __nv_bfloat16 Bs[128 * 72];

    float acc[2][8][4];
#pragma unroll
    for (int mi = 0; mi < 2; mi++)
#pragma unroll
        for (int ni = 0; ni < 8; ni++)
#pragma unroll
            for (int x = 0; x < 4; x++) acc[mi][ni][x] = 0.f;

    const int ldr = tid >> 3, ldc = (tid & 7) * 8;   // loader: row, col8
    uint4 ra[4], rb[4];
#pragma unroll
    for (int j = 0; j < 4; j++) {
        int r = ldr + 32 * j;
        ra[j] = *(const uint4*)&X[(size_t)(m0 + r) * DMn + ldc];
        rb[j] = *(const uint4*)&W[(size_t)(n0 + r) * DMn + ldc];
    }

    for (int kc = 0; kc < 8; kc++) {
        __syncthreads();
#pragma unroll
        for (int j = 0; j < 4; j++) {
            int r = ldr + 32 * j;
            *(uint4*)&As[r * 72 + ldc] = ra[j];
            *(uint4*)&Bs[r * 72 + ldc] = rb[j];
        }
        __syncthreads();
        if (kc < 7) {
            int kk = (kc + 1) * 64;
#pragma unroll
            for (int j = 0; j < 4; j++) {
                int r = ldr + 32 * j;
                ra[j] = *(const uint4*)&X[(size_t)(m0 + r) * DMn + kk + ldc];
                rb[j] = *(const uint4*)&W[(size_t)(n0 + r) * DMn + kk + ldc];
            }
        }
#pragma unroll
        for (int ks = 0; ks < 64; ks += 16) {
            uint32_t af[2][4];
#pragma unroll
            for (int mi = 0; mi < 2; mi++) {
                int ar = wm * 32 + mi * 16;
                af[mi][0] = *(const uint32_t*)&As[(ar + gq) * 72 + ks + 2 * tq];
                af[mi][1] = *(const uint32_t*)&As[(ar + gq + 8) * 72 + ks + 2 * tq];
                af[mi][2] = *(const uint32_t*)&As[(ar + gq) * 72 + ks + 2 * tq + 8];
                af[mi][3] = *(const uint32_t*)&As[(ar + gq + 8) * 72 + ks + 2 * tq + 8];
            }
#pragma unroll
            for (int ni = 0; ni < 8; ni++) {
                int br = wn * 64 + ni * 8 + gq;
                uint32_t bf[2];
                bf[0] = *(const uint32_t*)&Bs[br * 72 + ks + 2 * tq];
                bf[1] = *(const uint32_t*)&Bs[br * 72 + ks + 2 * tq + 8];
#pragma unroll
                for (int mi = 0; mi < 2; mi++) mma16816(acc[mi][ni], af[mi], bf);
            }
        }
    }

    // Epilogue: +bias, convert bf16, write to (bg,h,s,d) layout
#pragma unroll
    for (int ni = 0; ni < 8; ni++) {
        int cc = n0 + wn * 64 + ni * 8 + 2 * tq;
        float b0v = Bi[cc], b1v = Bi[cc + 1];
        int h = cc >> 6, d = cc & 63;
#pragma unroll
        for (int mi = 0; mi < 2; mi++) {
            int rbase = m0 + wm * 32 + mi * 16 + gq;
#pragma unroll
            for (int rr = 0; rr < 2; rr++) {
                int r = rbase + rr * 8;
                int bg = r >> 10, s = r & 1023;
                size_t off = ((size_t)(bg * Hn + h) * Sn + s) * DKn + d;
                float v0 = acc[mi][ni][rr * 2 + 0] + b0v;
                float v1 = acc[mi][ni][rr * 2 + 1] + b1v;
                *(__nv_bfloat162*)&O[off] = __floats2bfloat162_rn(v0, v1);
            }
        }
    }
}

// ---------------------------------------------------------------------------
// Attention v9: 32 q-rows x 1024 k per CTA, 512 threads (16 warps x 8 cols
// per chunk, 2 m-tiles share each B fragment). Same proven smem staging as
// round 6; register-resident exp; K traffic per output halved.
static constexpr int QR   = 32;
static constexpr int KSTR = 72;

__global__ __launch_bounds__(512, 1) void attn_kernel(float* __restrict__ out, int p_base, int write_p)
{
    __shared__ __nv_bfloat16 qs[QR * KSTR];
    __shared__ __nv_bfloat16 ksm[2 * 128 * KSTR];
    __shared__ float rsum[QR];

    const int qt = blockIdx.x, bgh = blockIdx.y;
    const int tid = threadIdx.x;
    const int w = tid >> 5, lane = tid & 31;
    const int gq = lane >> 2, tq = lane & 3;

    const __nv_bfloat16* qbase = g_q + (size_t)bgh * (Sn * DKn) + (size_t)qt * QR * DKn;
    const __nv_bfloat16* kbase = g_k + (size_t)bgh * (Sn * DKn);

    // q tile (32x64 bf16): 256 uint4
    if (tid < 256) {
        int r = tid >> 3, part = tid & 7;
        *(uint4*)&qs[r * KSTR + part * 8] = *(const uint4*)&qbase[r * DKn + part * 8];
    }
    if (tid < QR) rsum[tid] = 0.f;

    const float SCL = 1.0f / 1200.0f;  // 1/(sqrt(64)*150)
    const int ldr = tid >> 3, ldp = (tid & 7) * 8;   // k loader: 512 thr x 2 uint4

    uint4 pre[2];
#pragma unroll
    for (int j = 0; j < 2; j++)
        pre[j] = *(const uint4*)&kbase[(size_t)(ldr + 64 * j) * DKn + ldp];

    float acc[8][2][4];
#pragma unroll
    for (int c = 0; c < 8; c++)
#pragma unroll
        for (int mt = 0; mt < 2; mt++)
#pragma unroll
            for (int x = 0; x < 4; x++) acc[c][mt][x] = 0.f;

    uint32_t aq[2][4][4];   // [mt][k4][reg]
    float rs[4] = {0.f, 0.f, 0.f, 0.f};

#pragma unroll
    for (int c = 0; c < 8; c++) {
        __nv_bfloat16* kbuf = ksm + (c & 1) * 128 * KSTR;
#pragma unroll
        for (int j = 0; j < 2; j++)
            *(uint4*)&kbuf[(ldr + 64 * j) * KSTR + ldp] = pre[j];
        __syncthreads();
        if (c == 0) {
#pragma unroll
            for (int mt = 0; mt < 2; mt++)
#pragma unroll
                for (int k4 = 0; k4 < 4; k4++) {
                    int ks = k4 * 16;
                    int ar = mt * 16;
                    aq[mt][k4][0] = *(const uint32_t*)&qs[(ar + gq) * KSTR + ks + 2 * tq];
                    aq[mt][k4][1] = *(const uint32_t*)&qs[(ar + gq + 8) * KSTR + ks + 2 * tq];
                    aq[mt][k4][2] = *(const uint32_t*)&qs[(ar + gq) * KSTR + ks + 2 * tq + 8];
                    aq[mt][k4][3] = *(const uint32_t*)&qs[(ar + gq + 8) * KSTR + ks + 2 * tq + 8];
                }
        }
        if (c < 7) {
#pragma unroll
            for (int j = 0; j < 2; j++)
                pre[j] = *(const uint4*)&kbase[(size_t)((c + 1) * 128 + ldr + 64 * j) * DKn + ldp];
        }

#pragma unroll
        for (int k4 = 0; k4 < 4; k4++) {
            int ks = k4 * 16;
            int br = w * 8 + gq;
            uint32_t bf[2];
            bf[0] = *(const uint32_t*)&kbuf[br * KSTR + ks + 2 * tq];
            bf[1] = *(const uint32_t*)&kbuf[br * KSTR + ks + 2 * tq + 8];
            mma16816(acc[c][0], aq[0][k4], bf);
            mma16816(acc[c][1], aq[1][k4], bf);
        }

        // exp in place + rowsum partials
#pragma unroll
        for (int mt = 0; mt < 2; mt++) {
            float e0 = __expf(acc[c][mt][0] * SCL);
            float e1 = __expf(acc[c][mt][1] * SCL);
            float e2 = __expf(acc[c][mt][2] * SCL);
            float e3 = __expf(acc[c][mt][3] * SCL);
            acc[c][mt][0] = e0; acc[c][mt][1] = e1;
            acc[c][mt][2] = e2; acc[c][mt][3] = e3;
            rs[mt * 2]     += e0 + e1;   // row mt*16 + gq
            rs[mt * 2 + 1] += e2 + e3;   // row mt*16 + 8 + gq
        }
    }

    // rowsum: reduce over tq quad, then across warps via smem atomics
#pragma unroll
    for (int j = 0; j < 4; j++) {
        rs[j] += __shfl_xor_sync(0xffffffffu, rs[j], 1);
        rs[j] += __shfl_xor_sync(0xffffffffu, rs[j], 2);
    }
    if (tq == 0) {
        atomicAdd(&rsum[gq],      rs[0]);
        atomicAdd(&rsum[8 + gq],  rs[1]);
        atomicAdd(&rsum[16 + gq], rs[2]);
        atomicAdd(&rsum[24 + gq], rs[3]);
    }
    __syncthreads();
    if (tid < QR) rsum[tid] = 1.0f / rsum[tid];
    __syncthreads();

    float inv[4];
    inv[0] = rsum[gq];      inv[1] = rsum[8 + gq];
    inv[2] = rsum[16 + gq]; inv[3] = rsum[24 + gq];

    float* pout = out + p_base + (size_t)bgh * ((size_t)Sn * Sn) + (size_t)(qt * QR) * Sn;
    float* wbar = g_wbar + bgh * Sn;

#pragma unroll
    for (int c = 0; c < 8; c++) {
        int col = c * 128 + w * 8 + 2 * tq;
        float csx = 0.f, csy = 0.f;
#pragma unroll
        for (int mt = 0; mt < 2; mt++) {
            float v00 = acc[c][mt][0] * inv[mt * 2],     v01 = acc[c][mt][1] * inv[mt * 2];
            float v10 = acc[c][mt][2] * inv[mt * 2 + 1], v11 = acc[c][mt][3] * inv[mt * 2 + 1];
            if (write_p) {
                *(float2*)&pout[(size_t)(mt * 16 + gq) * Sn + col]     = make_float2(v00, v01);
                *(float2*)&pout[(size_t)(mt * 16 + 8 + gq) * Sn + col] = make_float2(v10, v11);
            }
            csx += v00 + v10;
            csy += v01 + v11;
        }
        // reduce over gq (lane bits 2..4): lanes 0..3 end with column totals
        csx += __shfl_xor_sync(0xffffffffu, csx, 4);
        csx += __shfl_xor_sync(0xffffffffu, csx, 8);
        csx += __shfl_xor_sync(0xffffffffu, csx, 16);
        csy += __shfl_xor_sync(0xffffffffu, csy, 4);
        csy += __shfl_xor_sync(0xffffffffu, csy, 8);
        csy += __shfl_xor_sync(0xffffffffu, csy, 16);
        if (lane < 4) {
            atomicAdd(&wbar[col], csx);
            atomicAdd(&wbar[col + 1], csy);
        }
    }
}

// ---------------------------------------------------------------------------
__global__ __launch_bounds__(256) void t_kernel(const float* __restrict__ value)
{
    __shared__ float wb[8][64];
    const int bg = blockIdx.x, kc = blockIdx.y;
    const int tid = threadIdx.x;

    for (int j = tid; j < 512; j += 256) {
        int h = j >> 6, k = j & 63;
        wb[h][k] = g_wbar[(bg * 8 + h) * Sn + kc * 64 + k] * (1.0f / 1024.0f);
    }
    __syncthreads();

    float a[8][2];
#pragma unroll
    for (int h = 0; h < 8; h++) { a[h][0] = 0.f; a[h][1] = 0.f; }

    const float* __restrict__ xv = value + (size_t)bg * (Sn * DMn) + (size_t)(kc * 64) * DMn;
#pragma unroll 4
    for (int k = 0; k < 64; k++) {
        float x0 = xv[k * DMn + tid];
        float x1 = xv[k * DMn + tid + 256];
#pragma unroll
        for (int h = 0; h < 8; h++) {
            a[h][0] += wb[h][k] * x0;
            a[h][1] += wb[h][k] * x1;
        }
    }
#pragma unroll
    for (int h = 0; h < 8; h++) {
        atomicAdd(&g_t[(bg * 8 + h) * DMn + tid],       a[h][0]);
        atomicAdd(&g_t[(bg * 8 + h) * DMn + tid + 256], a[h][1]);
    }
}

// ---------------------------------------------------------------------------
__global__ __launch_bounds__(512) void finalize2_kernel(
    const float* __restrict__ Wv, const float* __restrict__ bv,
    const float* __restrict__ Wo, const float* __restrict__ bo,
    float* __restrict__ out, int write_y)
{
    __shared__ float ts[8 * 512];
    __shared__ float fs[512];
    const int bg = blockIdx.x, tid = threadIdx.x;

#pragma unroll
    for (int j = 0; j < 8; j++) ts[j * 512 + tid] = g_t[bg * 4096 + j * 512 + tid];
    __syncthreads();

    {
        int h = tid >> 6, d = tid & 63;
        const float4* __restrict__ wr = (const float4*)(Wv + (size_t)tid * DMn);
        const float* th = ts + h * 512;
        float o0 = 0, o1 = 0, o2 = 0, o3 = 0;
#pragma unroll 8
        for (int c = 0; c < 128; c++) {
            float4 w4 = wr[c];
            o0 += th[4 * c + 0] * w4.x;
            o1 += th[4 * c + 1] * w4.y;
            o2 += th[4 * c + 2] * w4.z;
            o3 += th[4 * c + 3] * w4.w;
        }
        fs[d * 8 + h] = bv[tid] + ((o0 + o1) + (o2 + o3));
    }
    __syncthreads();

    if (write_y) {
        const float4* __restrict__ wr = (const float4*)(Wo + (size_t)tid * DMn);
        float o0 = 0, o1 = 0, o2 = 0, o3 = 0;
#pragma unroll 8
        for (int c = 0; c < 128; c++) {
            float4 w4 = wr[c];
            o0 += fs[4 * c + 0] * w4.x;
            o1 += fs[4 * c + 1] * w4.y;
            o2 += fs[4 * c + 2] * w4.z;
            o3 += fs[4 * c + 3] * w4.w;
        }
        out[bg * DMn + tid] = bo[tid] + ((o0 + o1) + (o2 + o3));
    }
}

// ---------------------------------------------------------------------------
extern "C" void kernel_launch(void* const* d_in, const int* in_sizes, int n_in,
                              void* d_out, int out_size)
{
    if (n_in < 11) return;
    const float* query = (const float*)d_in[0];
    const float* key   = (const float*)d_in[1];
    const float* value = (const float*)d_in[2];
    const float* Wq = (const float*)d_in[3];
    const float* bq = (const float*)d_in[4];
    const float* Wk = (const float*)d_in[5];
    const float* bk = (const float*)d_in[6];
    const float* Wv = (const float*)d_in[7];
    const float* bv = (const float*)d_in[8];
    const float* Wo = (const float*)d_in[9];
    const float* bo = (const float*)d_in[10];
    float* out = (float*)d_out;

    const int write_p = (out_size >= P_ELEMS) ? 1 : 0;
    const int p_base  = (out_size > P_ELEMS) ? Y_ELEMS : 0;
    const int write_y = (out_size == Y_ELEMS || out_size == Y_ELEMS + P_ELEMS) ? 1 : 0;

    const int X8 = (MROWS * DMn) / 8;      // 1572864
    const int W8 = (DMn * DMn) / 8;        // 32768

    zero_kernel<<<288, 256>>>();
    conv_kernel<<<X8 / 256, 256>>>(query, 0, X8);
    conv_kernel<<<X8 / 256, 256>>>(key,   1, X8);
    conv_kernel<<<W8 / 256, 256>>>(Wq,    2, W8);
    conv_kernel<<<W8 / 256, 256>>>(Wk,    3, W8);
    proj_kernel<<<dim3(192, 4), 256>>>(bq, 0);   // -> g_q
    proj_kernel<<<dim3(192, 4), 256>>>(bk, 1);   // -> g_k
    attn_kernel<<<dim3(32, 192), 512>>>(out, p_base, write_p);
    t_kernel<<<dim3(BG, 16), 256>>>(value);
    finalize2_kernel<<<BG, 512>>>(Wv, bv, Wo, bo, out, write_y);
}

// round 10
// speedup vs baseline: 1.0869x; 1.0252x over previous
#include <cuda_runtime.h>
#include <cuda_bf16.h>
#include <stdint.h>

// Problem constants
static constexpr int Bn = 4, Gn = 6, Hn = 8, Sn = 1024, DKn = 64, DMn = 512;
static constexpr int BG   = Bn * Gn;        // 24
static constexpr int BGH  = BG * Hn;        // 192
static constexpr int MROWS = BG * Sn;       // 24576
static constexpr int P_ELEMS = 201326592;   // 192*1024*1024
static constexpr int Y_ELEMS = BG * DMn;    // 12288

// alpha = log2(e) / (sqrt(64) * 150): folded into q at projection
static constexpr float ALPHA = 1.4426950408889634f / 1200.0f;

// Scratch (__device__ globals: allocation-free)
__device__ __align__(16) __nv_bfloat16 g_xq[(size_t)MROWS * DMn];  // bf16 inputs
__device__ __align__(16) __nv_bfloat16 g_xk[(size_t)MROWS * DMn];
__device__ __align__(16) __nv_bfloat16 g_wq[DMn * DMn];
__device__ __align__(16) __nv_bfloat16 g_wk[DMn * DMn];
__device__ __align__(16) __nv_bfloat16 g_q[(size_t)MROWS * DMn];   // (bg,h,s,d), pre-scaled by ALPHA
__device__ __align__(16) __nv_bfloat16 g_k[(size_t)MROWS * DMn];
__device__ __align__(16) float g_wbar[BGH * Sn];
__device__ __align__(16) float g_t[BG * Hn * DMn];

__device__ __forceinline__ void mma16816(float c[4], const uint32_t a[4], const uint32_t b[2]) {
    asm volatile(
        "mma.sync.aligned.m16n8k16.row.col.f32.bf16.bf16.f32 "
        "{%0,%1,%2,%3},{%4,%5,%6,%7},{%8,%9},{%0,%1,%2,%3};\n"
        : "+f"(c[0]), "+f"(c[1]), "+f"(c[2]), "+f"(c[3])
        : "r"(a[0]), "r"(a[1]), "r"(a[2]), "r"(a[3]), "r"(b[0]), "r"(b[1]));
}

__device__ __forceinline__ void ldsm_x4(uint32_t& r0, uint32_t& r1, uint32_t& r2, uint32_t& r3,
                                        uint32_t saddr) {
    asm volatile("ldmatrix.sync.aligned.m8n8.x4.shared.b16 {%0,%1,%2,%3}, [%4];"
                 : "=r"(r0), "=r"(r1), "=r"(r2), "=r"(r3) : "r"(saddr));
}

__device__ __forceinline__ float ex2f(float x) {
    float y;
    asm("ex2.approx.f32 %0, %1;" : "=f"(y) : "f"(x));
    return y;
}

// ---------------------------------------------------------------------------
// Fused prep: zero wbar/g_t + fp32->bf16 convert of xq/xk/Wq/Wk. One launch.
// Block ranges: [0,6144) xq, [6144,12288) xk, [12288,12416) wq,
// [12416,12544) wk, [12544,12832) zero.
__global__ __launch_bounds__(256) void prep_kernel(
    const float* __restrict__ query, const float* __restrict__ key,
    const float* __restrict__ Wq, const float* __restrict__ Wk)
{
    const int b = blockIdx.x, tid = threadIdx.x;
    if (b >= 12544) {
        int i = (b - 12544) * 1024 + tid * 4;
        float4 z = make_float4(0.f, 0.f, 0.f, 0.f);
        if (i < BGH * Sn) *(float4*)&g_wbar[i] = z;
        else              *(float4*)&g_t[i - BGH * Sn] = z;
        return;
    }
    const float* src;
    __nv_bfloat16* dst;
    int i;
    if (b < 6144)       { src = query; dst = g_xq; i = b * 256 + tid; }
    else if (b < 12288) { src = key;   dst = g_xk; i = (b - 6144) * 256 + tid; }
    else if (b < 12416) { src = Wq;    dst = g_wq; i = (b - 12288) * 256 + tid; }
    else                { src = Wk;    dst = g_wk; i = (b - 12416) * 256 + tid; }
    float4 a = ((const float4*)src)[i * 2];
    float4 c = ((const float4*)src)[i * 2 + 1];
    uint4 o;
    __nv_bfloat162 t0 = __floats2bfloat162_rn(a.x, a.y);
    __nv_bfloat162 t1 = __floats2bfloat162_rn(a.z, a.w);
    __nv_bfloat162 t2 = __floats2bfloat162_rn(c.x, c.y);
    __nv_bfloat162 t3 = __floats2bfloat162_rn(c.z, c.w);
    o.x = *(uint32_t*)&t0; o.y = *(uint32_t*)&t1;
    o.z = *(uint32_t*)&t2; o.w = *(uint32_t*)&t3;
    ((uint4*)dst)[i] = o;
}

// ---------------------------------------------------------------------------
// Projection: all-bf16. y = (x @ W^T + b) [* ALPHA if q] -> (bg,h,s,d) bf16.
__global__ __launch_bounds__(256) void proj_kernel(const float* __restrict__ Bi, int which)
{
    const __nv_bfloat16* __restrict__ X = which ? g_xk : g_xq;
    const __nv_bfloat16* __restrict__ W = which ? g_wk : g_wq;
    __nv_bfloat16* __restrict__ O = which ? g_k : g_q;
    const float oscale = which ? 1.0f : ALPHA;

    const int m0 = blockIdx.x * 128;
    const int n0 = blockIdx.y * 128;
    const int tid = threadIdx.x;
    const int w = tid >> 5, lane = tid & 31;
    const int gq = lane >> 2, tq = lane & 3;
    const int wm = w >> 1, wn = w & 1;   // 4x2 warps -> warp tile 32(m) x 64(n)

    __shared__ __nv_bfloat16 As[128 * 72];
    __shared__ __nv_bfloat16 Bs[128 * 72];

    float acc[2][8][4];
#pragma unroll
    for (int mi = 0; mi < 2; mi++)
#pragma unroll
        for (int ni = 0; ni < 8; ni++)
#pragma unroll
            for (int x = 0; x < 4; x++) acc[mi][ni][x] = 0.f;

    const int ldr = tid >> 3, ldc = (tid & 7) * 8;
    uint4 ra[4], rb[4];
#pragma unroll
    for (int j = 0; j < 4; j++) {
        int r = ldr + 32 * j;
        ra[j] = *(const uint4*)&X[(size_t)(m0 + r) * DMn + ldc];
        rb[j] = *(const uint4*)&W[(size_t)(n0 + r) * DMn + ldc];
    }

    for (int kc = 0; kc < 8; kc++) {
        __syncthreads();
#pragma unroll
        for (int j = 0; j < 4; j++) {
            int r = ldr + 32 * j;
            *(uint4*)&As[r * 72 + ldc] = ra[j];
            *(uint4*)&Bs[r * 72 + ldc] = rb[j];
        }
        __syncthreads();
        if (kc < 7) {
            int kk = (kc + 1) * 64;
#pragma unroll
            for (int j = 0; j < 4; j++) {
                int r = ldr + 32 * j;
                ra[j] = *(const uint4*)&X[(size_t)(m0 + r) * DMn + kk + ldc];
                rb[j] = *(const uint4*)&W[(size_t)(n0 + r) * DMn + kk + ldc];
            }
        }
#pragma unroll
        for (int ks = 0; ks < 64; ks += 16) {
            uint32_t af[2][4];
#pragma unroll
            for (int mi = 0; mi < 2; mi++) {
                int ar = wm * 32 + mi * 16;
                af[mi][0] = *(const uint32_t*)&As[(ar + gq) * 72 + ks + 2 * tq];
                af[mi][1] = *(const uint32_t*)&As[(ar + gq + 8) * 72 + ks + 2 * tq];
                af[mi][2] = *(const uint32_t*)&As[(ar + gq) * 72 + ks + 2 * tq + 8];
                af[mi][3] = *(const uint32_t*)&As[(ar + gq + 8) * 72 + ks + 2 * tq + 8];
            }
#pragma unroll
            for (int ni = 0; ni < 8; ni++) {
                int br = wn * 64 + ni * 8 + gq;
                uint32_t bf[2];
                bf[0] = *(const uint32_t*)&Bs[br * 72 + ks + 2 * tq];
                bf[1] = *(const uint32_t*)&Bs[br * 72 + ks + 2 * tq + 8];
#pragma unroll
                for (int mi = 0; mi < 2; mi++) mma16816(acc[mi][ni], af[mi], bf);
            }
        }
    }

    // Epilogue: +bias, optional alpha scale, bf16, (bg,h,s,d) layout
#pragma unroll
    for (int ni = 0; ni < 8; ni++) {
        int cc = n0 + wn * 64 + ni * 8 + 2 * tq;
        float b0v = Bi[cc], b1v = Bi[cc + 1];
        int h = cc >> 6, d = cc & 63;
#pragma unroll
        for (int mi = 0; mi < 2; mi++) {
            int rbase = m0 + wm * 32 + mi * 16 + gq;
#pragma unroll
            for (int rr = 0; rr < 2; rr++) {
                int r = rbase + rr * 8;
                int bg = r >> 10, s = r & 1023;
                size_t off = ((size_t)(bg * Hn + h) * Sn + s) * DKn + d;
                float v0 = (acc[mi][ni][rr * 2 + 0] + b0v) * oscale;
                float v1 = (acc[mi][ni][rr * 2 + 1] + b1v) * oscale;
                *(__nv_bfloat162*)&O[off] = __floats2bfloat162_rn(v0, v1);
            }
        }
    }
}

// ---------------------------------------------------------------------------
// Attention v10: 32 q-rows x 1024 k per CTA, 512 threads. LDSM B fragments,
// bare ex2 (scale pre-folded into q), register-resident exp values.
static constexpr int QR   = 32;
static constexpr int KSTR = 72;

__global__ __launch_bounds__(512, 1) void attn_kernel(float* __restrict__ out, int p_base, int write_p)
{
    __shared__ __nv_bfloat16 qs[QR * KSTR];
    __shared__ __nv_bfloat16 ksm[2 * 128 * KSTR];
    __shared__ float rsum[QR];

    const int qt = blockIdx.x, bgh = blockIdx.y;
    const int tid = threadIdx.x;
    const int w = tid >> 5, lane = tid & 31;
    const int gq = lane >> 2, tq = lane & 3;

    const __nv_bfloat16* qbase = g_q + (size_t)bgh * (Sn * DKn) + (size_t)qt * QR * DKn;
    const __nv_bfloat16* kbase = g_k + (size_t)bgh * (Sn * DKn);

    if (tid < 256) {
        int r = tid >> 3, part = tid & 7;
        *(uint4*)&qs[r * KSTR + part * 8] = *(const uint4*)&qbase[r * DKn + part * 8];
    }
    if (tid < QR) rsum[tid] = 0.f;

    const int ldr = tid >> 3, ldp = (tid & 7) * 8;

    uint4 pre[2];
#pragma unroll
    for (int j = 0; j < 2; j++)
        pre[j] = *(const uint4*)&kbase[(size_t)(ldr + 64 * j) * DKn + ldp];

    float acc[8][2][4];
#pragma unroll
    for (int c = 0; c < 8; c++)
#pragma unroll
        for (int mt = 0; mt < 2; mt++)
#pragma unroll
            for (int x = 0; x < 4; x++) acc[c][mt][x] = 0.f;

    uint32_t aq[2][4][4];   // [mt][k4][reg]
    float rs[4] = {0.f, 0.f, 0.f, 0.f};

    // LDSM source addresses (byte, shared space): lane l -> row w*8+(l&7),
    // k-col (l>>3)*8 within the chunk row. Second LDSM at +64B (k offset 32).
    const uint32_t ksm_s0 = (uint32_t)__cvta_generic_to_shared(ksm)
                          + ((w * 8 + (lane & 7)) * KSTR + (lane >> 3) * 8) * 2;
    const uint32_t kbuf_stride = 128 * KSTR * 2;  // bytes per buffer

#pragma unroll
    for (int c = 0; c < 8; c++) {
        __nv_bfloat16* kbuf = ksm + (c & 1) * 128 * KSTR;
#pragma unroll
        for (int j = 0; j < 2; j++)
            *(uint4*)&kbuf[(ldr + 64 * j) * KSTR + ldp] = pre[j];
        __syncthreads();
        if (c == 0) {
#pragma unroll
            for (int mt = 0; mt < 2; mt++)
#pragma unroll
                for (int k4 = 0; k4 < 4; k4++) {
                    int ks = k4 * 16;
                    int ar = mt * 16;
                    aq[mt][k4][0] = *(const uint32_t*)&qs[(ar + gq) * KSTR + ks + 2 * tq];
                    aq[mt][k4][1] = *(const uint32_t*)&qs[(ar + gq + 8) * KSTR + ks + 2 * tq];
                    aq[mt][k4][2] = *(const uint32_t*)&qs[(ar + gq) * KSTR + ks + 2 * tq + 8];
                    aq[mt][k4][3] = *(const uint32_t*)&qs[(ar + gq + 8) * KSTR + ks + 2 * tq + 8];
                }
        }
        if (c < 7) {
#pragma unroll
            for (int j = 0; j < 2; j++)
                pre[j] = *(const uint4*)&kbase[(size_t)((c + 1) * 128 + ldr + 64 * j) * DKn + ldp];
        }

        // B fragments via 2x ldmatrix.x4: tiles (k4,frag) = (0,0)(0,1)(1,0)(1,1), then k4=2,3
        uint32_t saddr = ksm_s0 + (c & 1) * kbuf_stride;
        uint32_t b0, b1, b2, b3, b4, b5, b6, b7;
        ldsm_x4(b0, b1, b2, b3, saddr);
        ldsm_x4(b4, b5, b6, b7, saddr + 64);

        {
            uint32_t bf0[2] = {b0, b1}, bf1[2] = {b2, b3};
            uint32_t bf2[2] = {b4, b5}, bf3[2] = {b6, b7};
            mma16816(acc[c][0], aq[0][0], bf0); mma16816(acc[c][1], aq[1][0], bf0);
            mma16816(acc[c][0], aq[0][1], bf1); mma16816(acc[c][1], aq[1][1], bf1);
            mma16816(acc[c][0], aq[0][2], bf2); mma16816(acc[c][1], aq[1][2], bf2);
            mma16816(acc[c][0], aq[0][3], bf3); mma16816(acc[c][1], aq[1][3], bf3);
        }

        // exp2 in place + rowsum partials (scale already folded into q)
#pragma unroll
        for (int mt = 0; mt < 2; mt++) {
            float e0 = ex2f(acc[c][mt][0]);
            float e1 = ex2f(acc[c][mt][1]);
            float e2 = ex2f(acc[c][mt][2]);
            float e3 = ex2f(acc[c][mt][3]);
            acc[c][mt][0] = e0; acc[c][mt][1] = e1;
            acc[c][mt][2] = e2; acc[c][mt][3] = e3;
            rs[mt * 2]     += e0 + e1;
            rs[mt * 2 + 1] += e2 + e3;
        }
    }

#pragma unroll
    for (int j = 0; j < 4; j++) {
        rs[j] += __shfl_xor_sync(0xffffffffu, rs[j], 1);
        rs[j] += __shfl_xor_sync(0xffffffffu, rs[j], 2);
    }
    if (tq == 0) {
        atomicAdd(&rsum[gq],      rs[0]);
        atomicAdd(&rsum[8 + gq],  rs[1]);
        atomicAdd(&rsum[16 + gq], rs[2]);
        atomicAdd(&rsum[24 + gq], rs[3]);
    }
    __syncthreads();
    if (tid < QR) rsum[tid] = 1.0f / rsum[tid];
    __syncthreads();

    float inv[4];
    inv[0] = rsum[gq];      inv[1] = rsum[8 + gq];
    inv[2] = rsum[16 + gq]; inv[3] = rsum[24 + gq];

    float* pout = out + p_base + (size_t)bgh * ((size_t)Sn * Sn) + (size_t)(qt * QR) * Sn;
    float* wbar = g_wbar + bgh * Sn;

#pragma unroll
    for (int c = 0; c < 8; c++) {
        int col = c * 128 + w * 8 + 2 * tq;
        float csx = 0.f, csy = 0.f;
#pragma unroll
        for (int mt = 0; mt < 2; mt++) {
            float v00 = acc[c][mt][0] * inv[mt * 2],     v01 = acc[c][mt][1] * inv[mt * 2];
            float v10 = acc[c][mt][2] * inv[mt * 2 + 1], v11 = acc[c][mt][3] * inv[mt * 2 + 1];
            if (write_p) {
                *(float2*)&pout[(size_t)(mt * 16 + gq) * Sn + col]     = make_float2(v00, v01);
                *(float2*)&pout[(size_t)(mt * 16 + 8 + gq) * Sn + col] = make_float2(v10, v11);
            }
            csx += v00 + v10;
            csy += v01 + v11;
        }
        csx += __shfl_xor_sync(0xffffffffu, csx, 4);
        csx += __shfl_xor_sync(0xffffffffu, csx, 8);
        csx += __shfl_xor_sync(0xffffffffu, csx, 16);
        csy += __shfl_xor_sync(0xffffffffu, csy, 4);
        csy += __shfl_xor_sync(0xffffffffu, csy, 8);
        csy += __shfl_xor_sync(0xffffffffu, csy, 16);
        if (lane < 4) {
            atomicAdd(&wbar[col], csx);
            atomicAdd(&wbar[col + 1], csy);
        }
    }
}

// ---------------------------------------------------------------------------
__global__ __launch_bounds__(256) void t_kernel(const float* __restrict__ value)
{
    __shared__ float wb[8][64];
    const int bg = blockIdx.x, kc = blockIdx.y;
    const int tid = threadIdx.x;

    for (int j = tid; j < 512; j += 256) {
        int h = j >> 6, k = j & 63;
        wb[h][k] = g_wbar[(bg * 8 + h) * Sn + kc * 64 + k] * (1.0f / 1024.0f);
    }
    __syncthreads();

    float a[8][2];
#pragma unroll
    for (int h = 0; h < 8; h++) { a[h][0] = 0.f; a[h][1] = 0.f; }

    const float* __restrict__ xv = value + (size_t)bg * (Sn * DMn) + (size_t)(kc * 64) * DMn;
#pragma unroll 4
    for (int k = 0; k < 64; k++) {
        float x0 = xv[k * DMn + tid];
        float x1 = xv[k * DMn + tid + 256];
#pragma unroll
        for (int h = 0; h < 8; h++) {
            a[h][0] += wb[h][k] * x0;
            a[h][1] += wb[h][k] * x1;
        }
    }
#pragma unroll
    for (int h = 0; h < 8; h++) {
        atomicAdd(&g_t[(bg * 8 + h) * DMn + tid],       a[h][0]);
        atomicAdd(&g_t[(bg * 8 + h) * DMn + tid + 256], a[h][1]);
    }
}

// ---------------------------------------------------------------------------
__global__ __launch_bounds__(512) void finalize2_kernel(
    const float* __restrict__ Wv, const float* __restrict__ bv,
    const float* __restrict__ Wo, const float* __restrict__ bo,
    float* __restrict__ out, int write_y)
{
    __shared__ float ts[8 * 512];
    __shared__ float fs[512];
    const int bg = blockIdx.x, tid = threadIdx.x;

#pragma unroll
    for (int j = 0; j < 8; j++) ts[j * 512 + tid] = g_t[bg * 4096 + j * 512 + tid];
    __syncthreads();

    {
        int h = tid >> 6, d = tid & 63;
        const float4* __restrict__ wr = (const float4*)(Wv + (size_t)tid * DMn);
        const float* th = ts + h * 512;
        float o0 = 0, o1 = 0, o2 = 0, o3 = 0;
#pragma unroll 8
        for (int c = 0; c < 128; c++) {
            float4 w4 = wr[c];
            o0 += th[4 * c + 0] * w4.x;
            o1 += th[4 * c + 1] * w4.y;
            o2 += th[4 * c + 2] * w4.z;
            o3 += th[4 * c + 3] * w4.w;
        }
        fs[d * 8 + h] = bv[tid] + ((o0 + o1) + (o2 + o3));
    }
    __syncthreads();

    if (write_y) {
        const float4* __restrict__ wr = (const float4*)(Wo + (size_t)tid * DMn);
        float o0 = 0, o1 = 0, o2 = 0, o3 = 0;
#pragma unroll 8
        for (int c = 0; c < 128; c++) {
            float4 w4 = wr[c];
            o0 += fs[4 * c + 0] * w4.x;
            o1 += fs[4 * c + 1] * w4.y;
            o2 += fs[4 * c + 2] * w4.z;
            o3 += fs[4 * c + 3] * w4.w;
        }
        out[bg * DMn + tid] = bo[tid] + ((o0 + o1) + (o2 + o3));
    }
}

// ---------------------------------------------------------------------------
extern "C" void kernel_launch(void* const* d_in, const int* in_sizes, int n_in,
                              void* d_out, int out_size)
{
    if (n_in < 11) return;
    const float* query = (const float*)d_in[0];
    const float* key   = (const float*)d_in[1];
    const float* value = (const float*)d_in[2];
    const float* Wq = (const float*)d_in[3];
    const float* bq = (const float*)d_in[4];
    const float* Wk = (const float*)d_in[5];
    const float* bk = (const float*)d_in[6];
    const float* Wv = (const float*)d_in[7];
    const float* bv = (const float*)d_in[8];
    const float* Wo = (const float*)d_in[9];
    const float* bo = (const float*)d_in[10];
    float* out = (float*)d_out;

    const int write_p = (out_size >= P_ELEMS) ? 1 : 0;
    const int p_base  = (out_size > P_ELEMS) ? Y_ELEMS : 0;
    const int write_y = (out_size == Y_ELEMS || out_size == Y_ELEMS + P_ELEMS) ? 1 : 0;

    prep_kernel<<<12832, 256>>>(query, key, Wq, Wk);          // launch 1
    proj_kernel<<<dim3(192, 4), 256>>>(bq, 0);                // launch 2 -> g_q (scaled)
    proj_kernel<<<dim3(192, 4), 256>>>(bk, 1);                // launch 3 -> g_k
    attn_kernel<<<dim3(32, 192), 512>>>(out, p_base, write_p); // launch 4 (capture slot)
    t_kernel<<<dim3(BG, 16), 256>>>(value);
    finalize2_kernel<<<BG, 512>>>(Wv, bv, Wo, bo, out, write_y);
}